// round 1
// baseline (speedup 1.0000x reference)
#include <cuda_runtime.h>
#include <math.h>

#define NNODES 50000
#define NEDGES 1600000
#define HDIM   64
#define EMBDIM 192
#define CDIM   16

// ---------------- scratch (static device globals; no allocation) -------------
__device__ __align__(16) float d_h[NNODES * HDIM];     // per-layer GEMM output
__device__ __align__(16) float d_emb[NNODES * EMBDIM]; // concat of 3 layer outputs
__device__ float d_dis[NNODES];                        // D^-1/2
__device__ int   d_count[NNODES];
__device__ int   d_rowptr[NNODES + 1];
__device__ int   d_cursor[NNODES];
__device__ int   d_csrcol[NEDGES];
__device__ int   d_bsum[64];

// ---------------- CSR build --------------------------------------------------
__global__ void k_zero() {
    int i = blockIdx.x * blockDim.x + threadIdx.x;
    if (i < NNODES) d_count[i] = 0;
}

__global__ void k_hist(const int* __restrict__ ei) {
    int e = blockIdx.x * blockDim.x + threadIdx.x;
    if (e < NEDGES) atomicAdd(&d_count[ei[e]], 1);
}

// block-level exclusive scan of counts (tile=1024) + degree norm
__global__ void k_scan1() {
    __shared__ int warpsum[32];
    int b = blockIdx.x;
    int i = b * 1024 + threadIdx.x;
    int c = (i < NNODES) ? d_count[i] : 0;
    int lane = threadIdx.x & 31, wid = threadIdx.x >> 5;
    int v = c;
#pragma unroll
    for (int o = 1; o < 32; o <<= 1) {
        int t = __shfl_up_sync(0xffffffffu, v, o);
        if (lane >= o) v += t;
    }
    if (lane == 31) warpsum[wid] = v;
    __syncthreads();
    if (wid == 0) {
        int w = warpsum[lane];
#pragma unroll
        for (int o = 1; o < 32; o <<= 1) {
            int t = __shfl_up_sync(0xffffffffu, w, o);
            if (lane >= o) w += t;
        }
        warpsum[lane] = w;
    }
    __syncthreads();
    int off = (wid > 0) ? warpsum[wid - 1] : 0;
    int incl = v + off;
    if (i < NNODES) {
        d_rowptr[i] = incl - c;                 // local exclusive prefix
        d_dis[i] = rsqrtf((float)(c + 1));      // deg = in-deg + self-loop >= 1
    }
    if (threadIdx.x == 1023) d_bsum[b] = incl;  // block total
}

// scan of block sums (<=64 blocks), in-place exclusive
__global__ void k_scan2(int nb) {
    __shared__ int s[64];
    int t = threadIdx.x;
    s[t] = (t < nb) ? d_bsum[t] : 0;
    __syncthreads();
#pragma unroll
    for (int o = 1; o < 64; o <<= 1) {
        int a = (t >= o) ? s[t - o] : 0;
        __syncthreads();
        s[t] += a;
        __syncthreads();
    }
    int ex = (t > 0) ? s[t - 1] : 0;
    d_bsum[t] = ex;
}

__global__ void k_addoff() {
    int i = blockIdx.x * 1024 + threadIdx.x;
    if (i < NNODES) {
        int r = d_rowptr[i] + d_bsum[i >> 10];
        d_rowptr[i] = r;
        d_cursor[i] = r;
    }
    if (i == 0) d_rowptr[NNODES] = NEDGES;
}

__global__ void k_scatter(const int* __restrict__ ei) {
    int e = blockIdx.x * blockDim.x + threadIdx.x;
    if (e < NEDGES) {
        int r = ei[e];
        int p = atomicAdd(&d_cursor[r], 1);
        d_csrcol[p] = ei[NEDGES + e];
    }
}

// ---------------- dense GEMM: h = in @ W  (K=64, Nout=64) -------------------
// block = 256 threads, 64 rows per block, full K and N tiles in smem.
__global__ void k_gemm(const float* __restrict__ xext, int inoff, int istride,
                       const float* __restrict__ W) {
    __shared__ float Xs[64][65];
    __shared__ __align__(16) float Ws[64][68];
    const float* in = xext ? xext : (const float*)d_emb;
    int tid = threadIdx.x;
    int bm = blockIdx.x * 64;
#pragma unroll
    for (int i = 0; i < 16; i++) {
        int idx = tid + i * 256;
        Ws[idx >> 6][idx & 63] = W[idx];
    }
#pragma unroll
    for (int i = 0; i < 16; i++) {
        int idx = tid + i * 256;
        int r = idx >> 6, k = idx & 63;
        int gr = bm + r;
        Xs[r][k] = (gr < NNODES) ? in[gr * istride + inoff + k] : 0.0f;
    }
    __syncthreads();
    int tx = tid & 15, ty = tid >> 4;
    float c[4][4] = {};
#pragma unroll
    for (int k = 0; k < 64; k++) {
        float a0 = Xs[ty * 4 + 0][k];
        float a1 = Xs[ty * 4 + 1][k];
        float a2 = Xs[ty * 4 + 2][k];
        float a3 = Xs[ty * 4 + 3][k];
        float4 bv = *(const float4*)&Ws[k][tx * 4];
        c[0][0] += a0 * bv.x; c[0][1] += a0 * bv.y; c[0][2] += a0 * bv.z; c[0][3] += a0 * bv.w;
        c[1][0] += a1 * bv.x; c[1][1] += a1 * bv.y; c[1][2] += a1 * bv.z; c[1][3] += a1 * bv.w;
        c[2][0] += a2 * bv.x; c[2][1] += a2 * bv.y; c[2][2] += a2 * bv.z; c[2][3] += a2 * bv.w;
        c[3][0] += a3 * bv.x; c[3][1] += a3 * bv.y; c[3][2] += a3 * bv.z; c[3][3] += a3 * bv.w;
    }
#pragma unroll
    for (int i = 0; i < 4; i++) {
        int gr = bm + ty * 4 + i;
        if (gr < NNODES) {
            float4 v = make_float4(c[i][0], c[i][1], c[i][2], c[i][3]);
            *(float4*)&d_h[gr * 64 + tx * 4] = v;
        }
    }
}

// ---------------- fused aggregate + self-loop + bias + relu + l2norm --------
// one warp per node; lanes 0-15 handle edge 2t, lanes 16-31 edge 2t+1;
// each lane owns a float4 slice of the 64-wide feature vector.
__global__ void k_agg(const float* __restrict__ bias, int loff) {
    int warp = (blockIdx.x * blockDim.x + threadIdx.x) >> 5;
    if (warp >= NNODES) return;
    int lane = threadIdx.x & 31;
    int half = lane >> 4, l16 = lane & 15;
    int i = warp;
    int s = d_rowptr[i];
    int cnt = d_rowptr[i + 1] - s;
    float di = d_dis[i];
    float4 acc = make_float4(0.f, 0.f, 0.f, 0.f);
    for (int t = 0; 2 * t < cnt; t++) {
        int e = s + 2 * t + half;
        if (2 * t + half < cnt) {
            int c = d_csrcol[e];
            float w = di * d_dis[c];
            float4 hv = *(const float4*)&d_h[c * 64 + l16 * 4];
            acc.x += hv.x * w; acc.y += hv.y * w;
            acc.z += hv.z * w; acc.w += hv.w * w;
        }
    }
    // fold upper half into lower half
    acc.x += __shfl_down_sync(0xffffffffu, acc.x, 16);
    acc.y += __shfl_down_sync(0xffffffffu, acc.y, 16);
    acc.z += __shfl_down_sync(0xffffffffu, acc.z, 16);
    acc.w += __shfl_down_sync(0xffffffffu, acc.w, 16);
    if (half == 0) {
        float ws = di * di;  // self-loop norm
        float4 hv = *(const float4*)&d_h[i * 64 + l16 * 4];
        acc.x += hv.x * ws; acc.y += hv.y * ws;
        acc.z += hv.z * ws; acc.w += hv.w * ws;
        float4 bv = *(const float4*)&bias[l16 * 4];
        acc.x = fmaxf(acc.x + bv.x, 0.f);
        acc.y = fmaxf(acc.y + bv.y, 0.f);
        acc.z = fmaxf(acc.z + bv.z, 0.f);
        acc.w = fmaxf(acc.w + bv.w, 0.f);
        float ss = acc.x * acc.x + acc.y * acc.y + acc.z * acc.z + acc.w * acc.w;
#pragma unroll
        for (int o = 8; o >= 1; o >>= 1)
            ss += __shfl_xor_sync(0x0000ffffu, ss, o);
        float inv = 1.0f / fmaxf(sqrtf(ss), 1e-12f);
        acc.x *= inv; acc.y *= inv; acc.z *= inv; acc.w *= inv;
        *(float4*)&d_emb[i * EMBDIM + loff + l16 * 4] = acc;
    }
}

// ---------------- final linear + log_softmax --------------------------------
__global__ void k_final(const float* __restrict__ Wl, const float* __restrict__ bl,
                        float* __restrict__ out) {
    __shared__ __align__(16) float Ws[EMBDIM * CDIM];
    __shared__ float bs[CDIM];
    int tid = threadIdx.x;
    for (int idx = tid; idx < EMBDIM * CDIM; idx += 256) Ws[idx] = Wl[idx];
    if (tid < CDIM) bs[tid] = bl[tid];
    __syncthreads();
    int i = blockIdx.x * 256 + tid;
    if (i >= NNODES) return;
    float acc[CDIM];
#pragma unroll
    for (int j = 0; j < CDIM; j++) acc[j] = bs[j];
    const float4* erow = (const float4*)&d_emb[i * EMBDIM];
#pragma unroll 4
    for (int kc = 0; kc < 48; kc++) {
        float4 ev = erow[kc];
        float ek4[4] = {ev.x, ev.y, ev.z, ev.w};
        int kb = kc * 4;
#pragma unroll
        for (int u = 0; u < 4; u++) {
            float ek = ek4[u];
            int k = kb + u;
#pragma unroll
            for (int j = 0; j < CDIM; j += 4) {
                float4 w = *(const float4*)&Ws[k * CDIM + j];
                acc[j + 0] += ek * w.x; acc[j + 1] += ek * w.y;
                acc[j + 2] += ek * w.z; acc[j + 3] += ek * w.w;
            }
        }
    }
    float m = acc[0];
#pragma unroll
    for (int j = 1; j < CDIM; j++) m = fmaxf(m, acc[j]);
    float sum = 0.f;
#pragma unroll
    for (int j = 0; j < CDIM; j++) sum += __expf(acc[j] - m);
    float lse = m + __logf(sum);
#pragma unroll
    for (int j = 0; j < CDIM; j++) out[i * CDIM + j] = acc[j] - lse;
}

// ---------------- launch -----------------------------------------------------
extern "C" void kernel_launch(void* const* d_in, const int* in_sizes, int n_in,
                              void* d_out, int out_size) {
    const float* x    = (const float*)d_in[0];
    const int*   ei   = (const int*)d_in[1];
    const float* W1   = (const float*)d_in[2];
    const float* b1   = (const float*)d_in[3];
    const float* W2   = (const float*)d_in[4];
    const float* b2   = (const float*)d_in[5];
    const float* W3   = (const float*)d_in[6];
    const float* b3   = (const float*)d_in[7];
    const float* Wlin = (const float*)d_in[8];
    const float* blin = (const float*)d_in[9];
    float* out = (float*)d_out;

    const int NB = (NNODES + 1023) / 1024;  // 49

    k_zero<<<(NNODES + 255) / 256, 256>>>();
    k_hist<<<(NEDGES + 255) / 256, 256>>>(ei);
    k_scan1<<<NB, 1024>>>();
    k_scan2<<<1, 64>>>(NB);
    k_addoff<<<NB, 1024>>>();
    k_scatter<<<(NEDGES + 255) / 256, 256>>>(ei);

    const int GEMM_BLOCKS = (NNODES + 63) / 64;         // 782
    const int AGG_BLOCKS  = (NNODES + 7) / 8;           // 6250 (8 warps/block)

    // layer 1
    k_gemm<<<GEMM_BLOCKS, 256>>>(x, 0, HDIM, W1);
    k_agg<<<AGG_BLOCKS, 256>>>(b1, 0);
    // layer 2
    k_gemm<<<GEMM_BLOCKS, 256>>>(nullptr, 0, EMBDIM, W2);
    k_agg<<<AGG_BLOCKS, 256>>>(b2, 64);
    // layer 3
    k_gemm<<<GEMM_BLOCKS, 256>>>(nullptr, 64, EMBDIM, W3);
    k_agg<<<AGG_BLOCKS, 256>>>(b3, 128);

    k_final<<<(NNODES + 255) / 256, 256>>>(Wlin, blin, out);
}

// round 2
// speedup vs baseline: 1.0200x; 1.0200x over previous
#include <cuda_runtime.h>
#include <cuda_fp16.h>
#include <math.h>

#define NNODES 50000
#define NEDGES 1600000
#define HDIM   64
#define EMBDIM 192
#define CDIM   16

// ---------------- scratch (static device globals; no allocation) -------------
__device__ __align__(16) __half d_h[NNODES * HDIM];    // per-layer GEMM output (fp16)
__device__ __align__(16) float d_emb[NNODES * EMBDIM]; // concat of 3 layer outputs
__device__ float d_dis[NNODES];                        // D^-1/2
__device__ int   d_count[NNODES];
__device__ int   d_rowptr[NNODES + 1];
__device__ int   d_cursor[NNODES];
__device__ __align__(16) int2 d_csrcw[NEDGES];         // {col, weight bits}
__device__ int   d_bsum[64];

// ---------------- CSR build --------------------------------------------------
__global__ void k_zero() {
    int i = blockIdx.x * blockDim.x + threadIdx.x;
    if (i < NNODES) d_count[i] = 0;
}

__global__ void k_hist(const int* __restrict__ ei) {
    int e = blockIdx.x * blockDim.x + threadIdx.x;
    if (e < NEDGES) atomicAdd(&d_count[ei[e]], 1);
}

// block-level exclusive scan of counts (tile=1024) + degree norm
__global__ void k_scan1() {
    __shared__ int warpsum[32];
    int b = blockIdx.x;
    int i = b * 1024 + threadIdx.x;
    int c = (i < NNODES) ? d_count[i] : 0;
    int lane = threadIdx.x & 31, wid = threadIdx.x >> 5;
    int v = c;
#pragma unroll
    for (int o = 1; o < 32; o <<= 1) {
        int t = __shfl_up_sync(0xffffffffu, v, o);
        if (lane >= o) v += t;
    }
    if (lane == 31) warpsum[wid] = v;
    __syncthreads();
    if (wid == 0) {
        int w = warpsum[lane];
#pragma unroll
        for (int o = 1; o < 32; o <<= 1) {
            int t = __shfl_up_sync(0xffffffffu, w, o);
            if (lane >= o) w += t;
        }
        warpsum[lane] = w;
    }
    __syncthreads();
    int off = (wid > 0) ? warpsum[wid - 1] : 0;
    int incl = v + off;
    if (i < NNODES) {
        d_rowptr[i] = incl - c;                 // local exclusive prefix
        d_dis[i] = rsqrtf((float)(c + 1));      // deg = in-deg + self-loop >= 1
    }
    if (threadIdx.x == 1023) d_bsum[b] = incl;  // block total
}

// scan of block sums (<=64 blocks), in-place exclusive
__global__ void k_scan2(int nb) {
    __shared__ int s[64];
    int t = threadIdx.x;
    s[t] = (t < nb) ? d_bsum[t] : 0;
    __syncthreads();
#pragma unroll
    for (int o = 1; o < 64; o <<= 1) {
        int a = (t >= o) ? s[t - o] : 0;
        __syncthreads();
        s[t] += a;
        __syncthreads();
    }
    int ex = (t > 0) ? s[t - 1] : 0;
    d_bsum[t] = ex;
}

__global__ void k_addoff() {
    int i = blockIdx.x * 1024 + threadIdx.x;
    if (i < NNODES) {
        int r = d_rowptr[i] + d_bsum[i >> 10];
        d_rowptr[i] = r;
        d_cursor[i] = r;
    }
    if (i == 0) d_rowptr[NNODES] = NEDGES;
}

// scatter col + precomputed edge weight dis[row]*dis[col]
__global__ void k_scatter(const int* __restrict__ ei) {
    int e = blockIdx.x * blockDim.x + threadIdx.x;
    if (e < NEDGES) {
        int r = ei[e];
        int c = ei[NEDGES + e];
        float w = d_dis[r] * d_dis[c];
        int p = atomicAdd(&d_cursor[r], 1);
        d_csrcw[p] = make_int2(c, __float_as_int(w));
    }
}

// ---------------- dense GEMM: h = in @ W  (K=64, Nout=64), fp16 output ------
__global__ void k_gemm(const float* __restrict__ xext, int inoff, int istride,
                       const float* __restrict__ W) {
    __shared__ float Xs[64][65];
    __shared__ __align__(16) float Ws[64][68];
    const float* in = xext ? xext : (const float*)d_emb;
    int tid = threadIdx.x;
    int bm = blockIdx.x * 64;
#pragma unroll
    for (int i = 0; i < 16; i++) {
        int idx = tid + i * 256;
        Ws[idx >> 6][idx & 63] = W[idx];
    }
#pragma unroll
    for (int i = 0; i < 16; i++) {
        int idx = tid + i * 256;
        int r = idx >> 6, k = idx & 63;
        int gr = bm + r;
        Xs[r][k] = (gr < NNODES) ? in[gr * istride + inoff + k] : 0.0f;
    }
    __syncthreads();
    int tx = tid & 15, ty = tid >> 4;
    float c[4][4] = {};
#pragma unroll
    for (int k = 0; k < 64; k++) {
        float a0 = Xs[ty * 4 + 0][k];
        float a1 = Xs[ty * 4 + 1][k];
        float a2 = Xs[ty * 4 + 2][k];
        float a3 = Xs[ty * 4 + 3][k];
        float4 bv = *(const float4*)&Ws[k][tx * 4];
        c[0][0] += a0 * bv.x; c[0][1] += a0 * bv.y; c[0][2] += a0 * bv.z; c[0][3] += a0 * bv.w;
        c[1][0] += a1 * bv.x; c[1][1] += a1 * bv.y; c[1][2] += a1 * bv.z; c[1][3] += a1 * bv.w;
        c[2][0] += a2 * bv.x; c[2][1] += a2 * bv.y; c[2][2] += a2 * bv.z; c[2][3] += a2 * bv.w;
        c[3][0] += a3 * bv.x; c[3][1] += a3 * bv.y; c[3][2] += a3 * bv.z; c[3][3] += a3 * bv.w;
    }
#pragma unroll
    for (int i = 0; i < 4; i++) {
        int gr = bm + ty * 4 + i;
        if (gr < NNODES) {
            __half2 h0 = __floats2half2_rn(c[i][0], c[i][1]);
            __half2 h1 = __floats2half2_rn(c[i][2], c[i][3]);
            uint2 v;
            v.x = *(unsigned*)&h0;
            v.y = *(unsigned*)&h1;
            *(uint2*)&d_h[gr * 64 + tx * 4] = v;
        }
    }
}

// ---------------- fused aggregate + self-loop + bias + relu + l2norm --------
// one warp per node; lanes 0-15 handle edge 2t, lanes 16-31 edge 2t+1;
// each lane owns a 4-wide slice of the 64-wide feature vector.
__global__ void __launch_bounds__(256) k_agg(const float* __restrict__ bias, int loff) {
    int warp = (blockIdx.x * blockDim.x + threadIdx.x) >> 5;
    if (warp >= NNODES) return;
    int lane = threadIdx.x & 31;
    int half = lane >> 4, l16 = lane & 15;
    int i = warp;
    int s = d_rowptr[i];
    int cnt = d_rowptr[i + 1] - s;
    float4 acc = make_float4(0.f, 0.f, 0.f, 0.f);
#pragma unroll 2
    for (int t = 0; 2 * t < cnt; t++) {
        int idx = 2 * t + half;
        if (idx < cnt) {
            int2 cw = d_csrcw[s + idx];
            float w = __int_as_float(cw.y);
            uint2 raw = *(const uint2*)&d_h[cw.x * 64 + l16 * 4];
            float2 f0 = __half22float2(*(const __half2*)&raw.x);
            float2 f1 = __half22float2(*(const __half2*)&raw.y);
            acc.x += f0.x * w; acc.y += f0.y * w;
            acc.z += f1.x * w; acc.w += f1.y * w;
        }
    }
    // fold upper half into lower half
    acc.x += __shfl_down_sync(0xffffffffu, acc.x, 16);
    acc.y += __shfl_down_sync(0xffffffffu, acc.y, 16);
    acc.z += __shfl_down_sync(0xffffffffu, acc.z, 16);
    acc.w += __shfl_down_sync(0xffffffffu, acc.w, 16);
    if (half == 0) {
        float di = d_dis[i];
        float ws = di * di;  // self-loop norm
        uint2 raw = *(const uint2*)&d_h[i * 64 + l16 * 4];
        float2 f0 = __half22float2(*(const __half2*)&raw.x);
        float2 f1 = __half22float2(*(const __half2*)&raw.y);
        acc.x += f0.x * ws; acc.y += f0.y * ws;
        acc.z += f1.x * ws; acc.w += f1.y * ws;
        float4 bv = *(const float4*)&bias[l16 * 4];
        acc.x = fmaxf(acc.x + bv.x, 0.f);
        acc.y = fmaxf(acc.y + bv.y, 0.f);
        acc.z = fmaxf(acc.z + bv.z, 0.f);
        acc.w = fmaxf(acc.w + bv.w, 0.f);
        float ss = acc.x * acc.x + acc.y * acc.y + acc.z * acc.z + acc.w * acc.w;
#pragma unroll
        for (int o = 8; o >= 1; o >>= 1)
            ss += __shfl_xor_sync(0x0000ffffu, ss, o);
        float inv = 1.0f / fmaxf(sqrtf(ss), 1e-12f);
        acc.x *= inv; acc.y *= inv; acc.z *= inv; acc.w *= inv;
        *(float4*)&d_emb[i * EMBDIM + loff + l16 * 4] = acc;
    }
}

// ---------------- final linear + log_softmax --------------------------------
__global__ void k_final(const float* __restrict__ Wl, const float* __restrict__ bl,
                        float* __restrict__ out) {
    __shared__ __align__(16) float Ws[EMBDIM * CDIM];
    __shared__ float bs[CDIM];
    int tid = threadIdx.x;
    for (int idx = tid; idx < EMBDIM * CDIM; idx += 256) Ws[idx] = Wl[idx];
    if (tid < CDIM) bs[tid] = bl[tid];
    __syncthreads();
    int i = blockIdx.x * 256 + tid;
    if (i >= NNODES) return;
    float acc[CDIM];
#pragma unroll
    for (int j = 0; j < CDIM; j++) acc[j] = bs[j];
    const float4* erow = (const float4*)&d_emb[i * EMBDIM];
#pragma unroll 4
    for (int kc = 0; kc < 48; kc++) {
        float4 ev = erow[kc];
        float ek4[4] = {ev.x, ev.y, ev.z, ev.w};
        int kb = kc * 4;
#pragma unroll
        for (int u = 0; u < 4; u++) {
            float ek = ek4[u];
            int k = kb + u;
#pragma unroll
            for (int j = 0; j < CDIM; j += 4) {
                float4 w = *(const float4*)&Ws[k * CDIM + j];
                acc[j + 0] += ek * w.x; acc[j + 1] += ek * w.y;
                acc[j + 2] += ek * w.z; acc[j + 3] += ek * w.w;
            }
        }
    }
    float m = acc[0];
#pragma unroll
    for (int j = 1; j < CDIM; j++) m = fmaxf(m, acc[j]);
    float sum = 0.f;
#pragma unroll
    for (int j = 0; j < CDIM; j++) sum += __expf(acc[j] - m);
    float lse = m + __logf(sum);
#pragma unroll
    for (int j = 0; j < CDIM; j++) out[i * CDIM + j] = acc[j] - lse;
}

// ---------------- launch -----------------------------------------------------
extern "C" void kernel_launch(void* const* d_in, const int* in_sizes, int n_in,
                              void* d_out, int out_size) {
    const float* x    = (const float*)d_in[0];
    const int*   ei   = (const int*)d_in[1];
    const float* W1   = (const float*)d_in[2];
    const float* b1   = (const float*)d_in[3];
    const float* W2   = (const float*)d_in[4];
    const float* b2   = (const float*)d_in[5];
    const float* W3   = (const float*)d_in[6];
    const float* b3   = (const float*)d_in[7];
    const float* Wlin = (const float*)d_in[8];
    const float* blin = (const float*)d_in[9];
    float* out = (float*)d_out;

    const int NB = (NNODES + 1023) / 1024;  // 49

    k_zero<<<(NNODES + 255) / 256, 256>>>();
    k_hist<<<(NEDGES + 255) / 256, 256>>>(ei);
    k_scan1<<<NB, 1024>>>();
    k_scan2<<<1, 64>>>(NB);
    k_addoff<<<NB, 1024>>>();
    k_scatter<<<(NEDGES + 255) / 256, 256>>>(ei);

    const int GEMM_BLOCKS = (NNODES + 63) / 64;         // 782
    const int AGG_BLOCKS  = (NNODES + 7) / 8;           // 6250 (8 warps/block)

    // layer 1
    k_gemm<<<GEMM_BLOCKS, 256>>>(x, 0, HDIM, W1);
    k_agg<<<AGG_BLOCKS, 256>>>(b1, 0);
    // layer 2
    k_gemm<<<GEMM_BLOCKS, 256>>>(nullptr, 0, EMBDIM, W2);
    k_agg<<<AGG_BLOCKS, 256>>>(b2, 64);
    // layer 3
    k_gemm<<<GEMM_BLOCKS, 256>>>(nullptr, 64, EMBDIM, W3);
    k_agg<<<AGG_BLOCKS, 256>>>(b3, 128);

    k_final<<<(NNODES + 255) / 256, 256>>>(Wlin, blin, out);
}